// round 1
// baseline (speedup 1.0000x reference)
#include <cuda_runtime.h>
#include <math.h>
#include <stdint.h>

// Problem constants
#define Nn   4096
#define KK   8
#define FD   512
#define NFW  532          // 512 + 4 + 16
#define EAW  1029         // 5 + 2*512
#define NKE  (Nn*KK)      // 32768

// Output layout (flattened float32 concat of the tuple)
#define NF_OFF   ((size_t)0)
#define EI_OFF   ((size_t)Nn*NFW)                 // 2179072
#define EA_OFF   (EI_OFF + (size_t)2*NKE)         // 2244608
#define OCC_OFF  (EA_OFF + (size_t)NKE*EAW)       // 35962880
#define MASK_OFF (OCC_OFF + (size_t)Nn)           // 35966976

#define DIST_T   108.0f
#define DIST_T2  11666.0f      // loose prefilter ( > 108^2 = 11664 )
#define SENT_D   1e30f
#define SENT_I   0x7fffffff

__device__ float4 g_xywh[Nn];   // cx, cy, w, h
__device__ int    g_dst [NKE];  // effective dst (0 if invalid)
__device__ float  g_nbd [NKE];  // neighbor distance (1e30 if invalid)

// ---------------------------------------------------------------------------
// K1: reid L2-normalize -> node_feat[:,0:512]; pos_normed -> [:,512:516];
//     stash xywh.
// ---------------------------------------------------------------------------
__global__ void k_norm(const float* __restrict__ reid,
                       const float* __restrict__ pos,
                       float* out)
{
    int i = blockIdx.x;
    int t = threadIdx.x;            // 128 threads
    const float* r = reid + (size_t)i * FD;

    float v[4];
    float s = 0.0f;
#pragma unroll
    for (int u = 0; u < 4; u++) { v[u] = r[t + 128*u]; s += v[u]*v[u]; }
#pragma unroll
    for (int o = 16; o > 0; o >>= 1) s += __shfl_xor_sync(0xffffffffu, s, o);
    __shared__ float ws[4];
    if ((t & 31) == 0) ws[t >> 5] = s;
    __syncthreads();
    float tot = ws[0] + ws[1] + ws[2] + ws[3];
    float den = sqrtf(tot) + 1e-12f;

    float* o = out + (size_t)i * NFW;
#pragma unroll
    for (int u = 0; u < 4; u++) o[t + 128*u] = v[u] / den;

    if (t == 0) {
        float x1 = pos[i*4+0], y1 = pos[i*4+1], x2 = pos[i*4+2], y2 = pos[i*4+3];
        float cx = 0.5f*(x1+x2), cy = 0.5f*(y1+y2);
        float w = x2 - x1, h = y2 - y1;
        g_xywh[i] = make_float4(cx, cy, w, h);
        o[512] = cx / 1920.0f;
        o[513] = cy / 1080.0f;
        o[514] = w  / 1920.0f;
        o[515] = h  / 1080.0f;
    }
}

// ---------------------------------------------------------------------------
// K2: per-row KNN (one warp per row), topology features, occ, stash edges.
// ---------------------------------------------------------------------------
__global__ void k_knn(const float* __restrict__ pos, float* out)
{
    __shared__ float2 sc[Nn];      // 32 KB of centers
    int t = threadIdx.x;           // 256 threads = 8 warps
    for (int j = t; j < Nn; j += 256) {
        float4 q = g_xywh[j];
        sc[j] = make_float2(q.x, q.y);
    }
    __syncthreads();

    int warp = t >> 5, lane = t & 31;
    int i = blockIdx.x * 8 + warp;
    float2 ci = sc[i];

    // per-lane sorted top-8 (ascending), static-indexed
    float dist[KK]; int idx[KK];
#pragma unroll
    for (int u = 0; u < KK; u++) { dist[u] = SENT_D; idx[u] = SENT_I; }

    for (int j = lane; j < Nn; j += 32) {
        float dx = ci.x - sc[j].x;
        float dy = ci.y - sc[j].y;
        float d2 = dx*dx + dy*dy;
        if (j != i && d2 <= DIST_T2) {
            float Dv = sqrtf(fmaxf(d2, 1e-12f));
            if (Dv <= DIST_T) {
                float kd = Dv; int ki = j;
#pragma unroll
                for (int u = 0; u < KK; u++) {
                    bool sw = (kd < dist[u]) || (kd == dist[u] && ki < idx[u]);
                    if (sw) {
                        float td = dist[u]; int ti = idx[u];
                        dist[u] = kd; idx[u] = ki;
                        kd = td; ki = ti;
                    }
                }
            }
        }
    }

    // warp merge: 8 rounds of packed (distBits,idx) min-reduce
    float res_d[KK]; int res_i[KK];
#pragma unroll
    for (int k = 0; k < KK; k++) {
        unsigned long long key =
            ((unsigned long long)__float_as_uint(dist[0]) << 32) | (unsigned)idx[0];
#pragma unroll
        for (int o = 16; o > 0; o >>= 1) {
            unsigned long long other = __shfl_xor_sync(0xffffffffu, key, o);
            if (other < key) key = other;
        }
        res_d[k] = __uint_as_float((unsigned)(key >> 32));
        res_i[k] = (int)(unsigned)(key & 0xffffffffull);
        unsigned long long mine =
            ((unsigned long long)__float_as_uint(dist[0]) << 32) | (unsigned)idx[0];
        if (mine == key) {
#pragma unroll
            for (int u = 0; u < KK-1; u++) { dist[u] = dist[u+1]; idx[u] = idx[u+1]; }
            dist[KK-1] = SENT_D; idx[KK-1] = SENT_I;
        }
    }

    if (lane == 0) {
        bool val[KK]; int ni[KK]; float nd[KK];
        float vx[KK], vy[KK];
#pragma unroll
        for (int k = 0; k < KK; k++) {
            val[k] = res_d[k] < 1e9f;
            ni[k]  = val[k] ? res_i[k] : 0;
            nd[k]  = val[k] ? res_d[k] : 0.0f;
            float2 cn = sc[ni[k]];
            vx[k] = cn.x - ci.x;
            vy[k] = cn.y - ci.y;
            g_dst[i*KK + k] = ni[k];
            g_nbd[i*KK + k] = val[k] ? res_d[k] : SENT_D;
        }
        float* nf = out + (size_t)i * NFW;
#pragma unroll
        for (int k = 0; k < KK; k++) nf[516 + k] = nd[k] / 1080.0f;

        const float LO = (float)(-1.0 + 1e-6);
        const float HI = (float)( 1.0 - 1e-6);
#pragma unroll
        for (int k = 0; k < KK-1; k++) {
            float a = 0.0f;
            if (val[k+1]) {
                float dot = vx[k]*vx[k+1] + vy[k]*vy[k+1];
                float n1 = sqrtf(vx[k]*vx[k] + vy[k]*vy[k]);
                float n2 = sqrtf(vx[k+1]*vx[k+1] + vy[k+1]*vy[k+1]);
                float cs = dot / (n1*n2 + 1e-12f);
                cs = fminf(fmaxf(cs, LO), HI);
                a = acosf(cs) * 57.29577951308232f;   // 180/pi
            }
            nf[524 + k] = a / 360.0f;
        }
        nf[531] = 0.0f;

        // occlusion flag vs nearest neighbor
        float occf = 0.0f;
        if (val[0]) {
            int nn = ni[0];
            float xi1 = pos[i*4+0],  yi1 = pos[i*4+1];
            float xi2 = pos[i*4+2],  yi2 = pos[i*4+3];
            float xn1 = pos[nn*4+0], yn1 = pos[nn*4+1];
            float xn2 = pos[nn*4+2], yn2 = pos[nn*4+3];
            float ox = fminf(xi2, xn2) - fmaxf(xi1, xn1);
            float oy = fminf(yi2, yn2) - fmaxf(yi1, yn1);
            float ov = fmaxf(ox, 0.0f) * fmaxf(oy, 0.0f);
            float w = xi2 - xi1, h = yi2 - yi1;
            occf = (ov > w*h*0.5f) ? 1.0f : 0.0f;
        }
        out[OCC_OFF + i] = occf;
    }
}

// ---------------------------------------------------------------------------
// K3: edge_attr (32768 x 1029), edge_index, mask. One block (128 thr) / edge.
// ---------------------------------------------------------------------------
__global__ void k_edge(const float* __restrict__ pos, float* out)
{
    int e = blockIdx.x;
    int t = threadIdx.x;            // 128 threads
    int i = e >> 3;

    bool valid = g_nbd[e] < 1e9f;
    int dst = g_dst[e];             // 0 if invalid
    float m = valid ? 1.0f : 0.0f;

    const float* nf = out;          // node_feat region (reid at cols [0,512))
    float* ea = out + EA_OFF + (size_t)e * EAW;

    // reid copies: 128 float4 per row, float4 loads (16B aligned: 532 % 4 == 0)
    const float4* rs4 = (const float4*)(nf + (size_t)i   * NFW);
    const float4* rd4 = (const float4*)(nf + (size_t)dst * NFW);
    float4 a = rs4[t];
    float4 b = rd4[t];
    float* oa = ea + 5   + 4*t;
    float* ob = ea + 517 + 4*t;
    oa[0] = a.x*m; oa[1] = a.y*m; oa[2] = a.z*m; oa[3] = a.w*m;
    ob[0] = b.x*m; ob[1] = b.y*m; ob[2] = b.z*m; ob[3] = b.w*m;

    if (t == 0) {
        float4 xi  = g_xywh[i];
        float4 xd4 = g_xywh[dst];
        float xd = (xi.x - xd4.x) / 1920.0f;
        float yd = (xi.y - xd4.y) / 1080.0f;

        float pi0 = pos[i*4+0],   pi1 = pos[i*4+1];
        float pi2 = pos[i*4+2],   pi3 = pos[i*4+3];
        float pd0 = pos[dst*4+0], pd1 = pos[dst*4+1];
        float pd2 = pos[dst*4+2], pd3 = pos[dst*4+3];
        float ix1 = fmaxf(pi0, pd0), iy1 = fmaxf(pi1, pd1);
        float ix2 = fminf(pi2, pd2), iy2 = fminf(pi3, pd3);
        float inter = fmaxf(ix2-ix1, 0.0f) * fmaxf(iy2-iy1, 0.0f);
        float ai = (pi2-pi0)*(pi3-pi1);
        float ad = (pd2-pd0)*(pd3-pd1);
        float iou = inter / (ai + ad - inter + 1e-12f);
        float lw = logf(xi.z / xd4.z);
        float lh = logf(xi.w / xd4.w);

        ea[0] = xd  * m;
        ea[1] = yd  * m;
        ea[2] = iou * m;
        ea[3] = lw  * m;
        ea[4] = lh  * m;

        out[EI_OFF + e]        = (float)i;
        out[EI_OFF + NKE + e]  = (float)dst;
        out[MASK_OFF + e]      = m;
    }
}

// ---------------------------------------------------------------------------
extern "C" void kernel_launch(void* const* d_in, const int* in_sizes, int n_in,
                              void* d_out, int out_size)
{
    const float* reid = (const float*)d_in[0];
    const float* pos  = (const float*)d_in[1];
    // d_in[2] = confs (unused by the reference forward)
    float* out = (float*)d_out;

    k_norm<<<Nn, 128>>>(reid, pos, out);
    k_knn <<<Nn/8, 256>>>(pos, out);
    k_edge<<<NKE, 128>>>(pos, out);
}

// round 2
// speedup vs baseline: 1.0261x; 1.0261x over previous
#include <cuda_runtime.h>
#include <math.h>
#include <stdint.h>

// Problem constants
#define Nn   4096
#define KK   8
#define FD   512
#define NFW  532          // 512 + 4 + 16
#define EAW  1029         // 5 + 2*512
#define NKE  (Nn*KK)      // 32768

// Output layout (flattened float32 concat of the tuple)
#define NF_OFF   ((size_t)0)
#define EI_OFF   ((size_t)Nn*NFW)                 // 2179072
#define EA_OFF   (EI_OFF + (size_t)2*NKE)         // 2244608
#define OCC_OFF  (EA_OFF + (size_t)NKE*EAW)       // 35962880
#define MASK_OFF (OCC_OFF + (size_t)Nn)           // 35966976

#define DIST_T   108.0f
#define DIST_T2  11666.0f      // loose prefilter ( > 108^2 = 11664 )
#define SENT_D   1e30f
#define SENT_I   0x7fffffff

__device__ float4 g_xywh[Nn];   // cx, cy, w, h
__device__ int    g_dst [NKE];  // effective dst (0 if invalid)
__device__ float  g_nbd [NKE];  // neighbor distance (1e30 if invalid)

// ---------------------------------------------------------------------------
// K1: reid L2-normalize -> node_feat[:,0:512]; pos_normed -> [:,512:516];
//     stash xywh. One warp per row, float4 I/O.
// ---------------------------------------------------------------------------
__global__ void k_norm(const float* __restrict__ reid,
                       const float* __restrict__ pos,
                       float* out)
{
    int warp = threadIdx.x >> 5, lane = threadIdx.x & 31;
    int i = blockIdx.x * 8 + warp;

    const float4* r = (const float4*)(reid + (size_t)i * FD);
    float4 v[4];
    float s = 0.0f;
#pragma unroll
    for (int u = 0; u < 4; u++) {
        v[u] = r[lane + 32*u];
        s += v[u].x*v[u].x + v[u].y*v[u].y + v[u].z*v[u].z + v[u].w*v[u].w;
    }
#pragma unroll
    for (int o = 16; o > 0; o >>= 1) s += __shfl_xor_sync(0xffffffffu, s, o);
    float inv = 1.0f / (sqrtf(s) + 1e-12f);

    float4* o4 = (float4*)(out + (size_t)i * NFW);
#pragma unroll
    for (int u = 0; u < 4; u++) {
        float4 w = v[u];
        w.x *= inv; w.y *= inv; w.z *= inv; w.w *= inv;
        o4[lane + 32*u] = w;
    }

    if (lane == 0) {
        float x1 = pos[i*4+0], y1 = pos[i*4+1], x2 = pos[i*4+2], y2 = pos[i*4+3];
        float cx = 0.5f*(x1+x2), cy = 0.5f*(y1+y2);
        float w = x2 - x1, h = y2 - y1;
        g_xywh[i] = make_float4(cx, cy, w, h);
        float* o = out + (size_t)i * NFW;
        o[512] = cx / 1920.0f;
        o[513] = cy / 1080.0f;
        o[514] = w  / 1920.0f;
        o[515] = h  / 1080.0f;
    }
}

// ---------------------------------------------------------------------------
// K2: per-row KNN (one warp per row), topology features, occ, stash edges.
// ---------------------------------------------------------------------------
__global__ void k_knn(const float* __restrict__ pos, float* out)
{
    __shared__ float2 sc[Nn];      // 32 KB of centers
    int t = threadIdx.x;           // 256 threads = 8 warps
    for (int j = t; j < Nn; j += 256) {
        float4 q = g_xywh[j];
        sc[j] = make_float2(q.x, q.y);
    }
    __syncthreads();

    int warp = t >> 5, lane = t & 31;
    int i = blockIdx.x * 8 + warp;
    float2 ci = sc[i];

    // per-lane sorted top-8 (ascending), static-indexed
    float dist[KK]; int idx[KK];
#pragma unroll
    for (int u = 0; u < KK; u++) { dist[u] = SENT_D; idx[u] = SENT_I; }

    for (int j = lane; j < Nn; j += 32) {
        float dx = ci.x - sc[j].x;
        float dy = ci.y - sc[j].y;
        float d2 = dx*dx + dy*dy;
        if (j != i && d2 <= DIST_T2) {
            float Dv = sqrtf(fmaxf(d2, 1e-12f));
            if (Dv <= DIST_T) {
                float kd = Dv; int ki = j;
#pragma unroll
                for (int u = 0; u < KK; u++) {
                    bool sw = (kd < dist[u]) || (kd == dist[u] && ki < idx[u]);
                    if (sw) {
                        float td = dist[u]; int ti = idx[u];
                        dist[u] = kd; idx[u] = ki;
                        kd = td; ki = ti;
                    }
                }
            }
        }
    }

    // warp merge: 8 rounds of packed (distBits,idx) min-reduce
    float res_d[KK]; int res_i[KK];
#pragma unroll
    for (int k = 0; k < KK; k++) {
        unsigned long long key =
            ((unsigned long long)__float_as_uint(dist[0]) << 32) | (unsigned)idx[0];
#pragma unroll
        for (int o = 16; o > 0; o >>= 1) {
            unsigned long long other = __shfl_xor_sync(0xffffffffu, key, o);
            if (other < key) key = other;
        }
        res_d[k] = __uint_as_float((unsigned)(key >> 32));
        res_i[k] = (int)(unsigned)(key & 0xffffffffull);
        unsigned long long mine =
            ((unsigned long long)__float_as_uint(dist[0]) << 32) | (unsigned)idx[0];
        if (mine == key) {
#pragma unroll
            for (int u = 0; u < KK-1; u++) { dist[u] = dist[u+1]; idx[u] = idx[u+1]; }
            dist[KK-1] = SENT_D; idx[KK-1] = SENT_I;
        }
    }

    if (lane == 0) {
        bool val[KK]; int ni[KK]; float nd[KK];
        float vx[KK], vy[KK];
#pragma unroll
        for (int k = 0; k < KK; k++) {
            val[k] = res_d[k] < 1e9f;
            ni[k]  = val[k] ? res_i[k] : 0;
            nd[k]  = val[k] ? res_d[k] : 0.0f;
            float2 cn = sc[ni[k]];
            vx[k] = cn.x - ci.x;
            vy[k] = cn.y - ci.y;
            g_dst[i*KK + k] = ni[k];
            g_nbd[i*KK + k] = val[k] ? res_d[k] : SENT_D;
        }
        float* nf = out + (size_t)i * NFW;
#pragma unroll
        for (int k = 0; k < KK; k++) nf[516 + k] = nd[k] / 1080.0f;

        const float LO = (float)(-1.0 + 1e-6);
        const float HI = (float)( 1.0 - 1e-6);
#pragma unroll
        for (int k = 0; k < KK-1; k++) {
            float a = 0.0f;
            if (val[k+1]) {
                float dot = vx[k]*vx[k+1] + vy[k]*vy[k+1];
                float n1 = sqrtf(vx[k]*vx[k] + vy[k]*vy[k]);
                float n2 = sqrtf(vx[k+1]*vx[k+1] + vy[k+1]*vy[k+1]);
                float cs = dot / (n1*n2 + 1e-12f);
                cs = fminf(fmaxf(cs, LO), HI);
                a = acosf(cs) * 57.29577951308232f;   // 180/pi
            }
            nf[524 + k] = a / 360.0f;
        }
        nf[531] = 0.0f;

        // occlusion flag vs nearest neighbor
        float occf = 0.0f;
        if (val[0]) {
            int nn = ni[0];
            float xi1 = pos[i*4+0],  yi1 = pos[i*4+1];
            float xi2 = pos[i*4+2],  yi2 = pos[i*4+3];
            float xn1 = pos[nn*4+0], yn1 = pos[nn*4+1];
            float xn2 = pos[nn*4+2], yn2 = pos[nn*4+3];
            float ox = fminf(xi2, xn2) - fmaxf(xi1, xn1);
            float oy = fminf(yi2, yn2) - fmaxf(yi1, yn1);
            float ov = fmaxf(ox, 0.0f) * fmaxf(oy, 0.0f);
            float w = xi2 - xi1, h = yi2 - yi1;
            occf = (ov > w*h*0.5f) ? 1.0f : 0.0f;
        }
        out[OCC_OFF + i] = occf;
    }
}

// ---------------------------------------------------------------------------
// K3: edge features. One block per NODE (256 threads), 8 edges each.
//     src reid loaded once into smem; dst reid streamed per edge.
// ---------------------------------------------------------------------------
__global__ void k_edge(const float* __restrict__ pos, float* out)
{
    __shared__ float sre[FD];
    int i = blockIdx.x;
    int t = threadIdx.x;            // 256 threads
    const float* nf = out;

    // load src reid once (rows are 16B-aligned: NFW % 4 == 0)
    if (t < 128) {
        ((float4*)sre)[t] = ((const float4*)(nf + (size_t)i * NFW))[t];
    }

    // threads 0..7: scalar features for edge k = t
    if (t < 8) {
        int e = i*KK + t;
        bool valid = g_nbd[e] < 1e9f;
        int dst = g_dst[e];
        float m = valid ? 1.0f : 0.0f;

        float4 xi  = g_xywh[i];
        float4 xd4 = g_xywh[dst];
        float xd = (xi.x - xd4.x) / 1920.0f;
        float yd = (xi.y - xd4.y) / 1080.0f;

        float pi0 = pos[i*4+0],   pi1 = pos[i*4+1];
        float pi2 = pos[i*4+2],   pi3 = pos[i*4+3];
        float pd0 = pos[dst*4+0], pd1 = pos[dst*4+1];
        float pd2 = pos[dst*4+2], pd3 = pos[dst*4+3];
        float ix1 = fmaxf(pi0, pd0), iy1 = fmaxf(pi1, pd1);
        float ix2 = fminf(pi2, pd2), iy2 = fminf(pi3, pd3);
        float inter = fmaxf(ix2-ix1, 0.0f) * fmaxf(iy2-iy1, 0.0f);
        float ai = (pi2-pi0)*(pi3-pi1);
        float ad = (pd2-pd0)*(pd3-pd1);
        float iou = inter / (ai + ad - inter + 1e-12f);
        float lw = logf(xi.z / xd4.z);
        float lh = logf(xi.w / xd4.w);

        float* ea = out + EA_OFF + (size_t)e * EAW;
        ea[0] = xd  * m;
        ea[1] = yd  * m;
        ea[2] = iou * m;
        ea[3] = lw  * m;
        ea[4] = lh  * m;

        out[EI_OFF + e]        = (float)i;
        out[EI_OFF + NKE + e]  = (float)dst;
        out[MASK_OFF + e]      = m;
    }
    __syncthreads();

#pragma unroll
    for (int k = 0; k < KK; k++) {
        int e = i*KK + k;
        bool valid = g_nbd[e] < 1e9f;
        int dst = g_dst[e];
        float m = valid ? 1.0f : 0.0f;

        float* ea = out + EA_OFF + (size_t)e * EAW;
        const float* rd = nf + (size_t)dst * NFW;

        // src reid from smem (coalesced scalar stores)
        ea[5 + t]        = sre[t]        * m;
        ea[5 + 256 + t]  = sre[256 + t]  * m;
        // dst reid streamed (coalesced loads, L2-resident)
        ea[517 + t]       = rd[t]       * m;
        ea[517 + 256 + t] = rd[256 + t] * m;
    }
}

// ---------------------------------------------------------------------------
extern "C" void kernel_launch(void* const* d_in, const int* in_sizes, int n_in,
                              void* d_out, int out_size)
{
    const float* reid = (const float*)d_in[0];
    const float* pos  = (const float*)d_in[1];
    // d_in[2] = confs (unused by the reference forward)
    float* out = (float*)d_out;

    k_norm<<<Nn/8, 256>>>(reid, pos, out);
    k_knn <<<Nn/8, 256>>>(pos, out);
    k_edge<<<Nn, 256>>>(pos, out);
}